// round 9
// baseline (speedup 1.0000x reference)
#include <cuda_runtime.h>
#include <cuda_bf16.h>

// y[i,a,b] = sum_{kj,kh,l} w[i,kj,kh,l] * U[a+kj-1, kh, b, l]   (zero pad on a+kj-1)
// U[ap,kh,b,l] = T(ap,kh,(b-1)%14, l+128) + T(ap,kh,b,l)
// T(ap,kh,b',c) = (0 <= b'+kh-1 < 14) ? x[c, ap, (b'+kh-2) mod 14] : 0

#define U_ELEMS (14 * 3 * 14 * 128)     // 75264
#define U_BLOCKS 294                     // 294*256 == 75264
#define GEMM_SMEM (16128 * 4)            // 64512 B: [9][14][128] floats

__device__ float g_U[U_ELEMS];          // [ap][kh][b][l]

__global__ void prep_kernel(const float* __restrict__ x) {
    int e = blockIdx.x * 256 + threadIdx.x;          // < 75264
    int l  = e & 127;
    int b  = (e >> 7) % 14;
    int kh = (e / (128 * 14)) % 3;
    int ap = e / (128 * 14 * 3);

    float val = 0.0f;
    int t = b + kh - 1;
    if (t >= 0 && t < 14) {
        int wsrc = t - 1; if (wsrc < 0) wsrc += 14;
        val += x[l * 196 + ap * 14 + wsrc];
    }
    int bm = b - 1; if (bm < 0) bm += 14;
    int t1 = bm + kh - 1;
    if (t1 >= 0 && t1 < 14) {
        int wsrc = t1 - 1; if (wsrc < 0) wsrc += 14;
        val += x[(l + 128) * 196 + ap * 14 + wsrc];
    }
    g_U[e] = val;
}

// Grid (a=14, i-tile=8), 512 threads = 16 warps.
// Warp owns 2 channels (i0 + 2*warp + {0,1}), all 14 b, full K=1152.
// Lanes split K: lane reads w[i][t*128 + lane*4 ..] (coalesced float4, natural layout)
// and u_s[t][b][lane*4 ..] (conflict-free LDS.128, reused for both channels).
// Final: shfl_xor butterfly over lanes, direct store to y. No w transpose, no smem reduce.
__global__ __launch_bounds__(512, 1)
void gemm_kernel(const float* __restrict__ w, float* __restrict__ y) {
    extern __shared__ float u_s[];       // [t=9][b=14][l=128] = 16128 floats

    const int a   = blockIdx.x;          // 0..13
    const int i0  = blockIdx.y * 32;
    const int tid = threadIdx.x;

    // ---- stage U rows ap = a-1 .. a+1 (zero outside [0,14)) ----
    float4* u4s = (float4*)u_s;
#pragma unroll
    for (int it = 0; it < 8; it++) {
        int idx = it * 512 + tid;                    // < 4096; valid < 4032
        if (idx < 4032) {
            int kj  = idx / 1344;                    // 5376/4
            int rem = idx - kj * 1344;
            int ap  = a - 1 + kj;
            float4 v = make_float4(0.f, 0.f, 0.f, 0.f);
            if (ap >= 0 && ap < 14) v = ((const float4*)g_U)[ap * 1344 + rem];
            u4s[idx] = v;
        }
    }
    __syncthreads();

    const int warp = tid >> 5;           // 0..15
    const int lane = tid & 31;
    const int ia = i0 + 2 * warp;        // channel pair

    float acc0[14], acc1[14];
#pragma unroll
    for (int b = 0; b < 14; b++) { acc0[b] = 0.f; acc1[b] = 0.f; }

    const float4* w4 = (const float4*)w;             // row stride 288 float4
    const float4* wp0 = w4 + ia * 288 + lane;
    const float4* wp1 = w4 + (ia + 1) * 288 + lane;
    const float4* u4 = (const float4*)u_s + lane;

#pragma unroll 3
    for (int t = 0; t < 9; t++) {
        float4 wv0 = wp0[t * 32];                    // coalesced LDG.128
        float4 wv1 = wp1[t * 32];
#pragma unroll
        for (int b = 0; b < 14; b++) {
            float4 uv = u4[t * 448 + b * 32];        // LDS.128, shared by both channels
            acc0[b] = fmaf(wv0.x, uv.x, acc0[b]);
            acc0[b] = fmaf(wv0.y, uv.y, acc0[b]);
            acc0[b] = fmaf(wv0.z, uv.z, acc0[b]);
            acc0[b] = fmaf(wv0.w, uv.w, acc0[b]);
            acc1[b] = fmaf(wv1.x, uv.x, acc1[b]);
            acc1[b] = fmaf(wv1.y, uv.y, acc1[b]);
            acc1[b] = fmaf(wv1.z, uv.z, acc1[b]);
            acc1[b] = fmaf(wv1.w, uv.w, acc1[b]);
        }
    }

    // ---- butterfly reduce across lanes; single-lane store per (i,b) ----
#pragma unroll
    for (int b = 0; b < 14; b++) {
        float s0 = acc0[b];
        s0 += __shfl_xor_sync(0xffffffffu, s0, 16);
        s0 += __shfl_xor_sync(0xffffffffu, s0, 8);
        s0 += __shfl_xor_sync(0xffffffffu, s0, 4);
        s0 += __shfl_xor_sync(0xffffffffu, s0, 2);
        s0 += __shfl_xor_sync(0xffffffffu, s0, 1);
        if (lane == b) y[ia * 196 + a * 14 + b] = s0;

        float s1 = acc1[b];
        s1 += __shfl_xor_sync(0xffffffffu, s1, 16);
        s1 += __shfl_xor_sync(0xffffffffu, s1, 8);
        s1 += __shfl_xor_sync(0xffffffffu, s1, 4);
        s1 += __shfl_xor_sync(0xffffffffu, s1, 2);
        s1 += __shfl_xor_sync(0xffffffffu, s1, 1);
        if (lane == b + 16) y[(ia + 1) * 196 + a * 14 + b] = s1;
    }
}

extern "C" void kernel_launch(void* const* d_in, const int* in_sizes, int n_in,
                              void* d_out, int out_size) {
    const float* x = (const float*)d_in[0];
    const float* w = (const float*)d_in[1];
    float* y = (float*)d_out;

    cudaFuncSetAttribute(gemm_kernel,
                         cudaFuncAttributeMaxDynamicSharedMemorySize, GEMM_SMEM);

    prep_kernel<<<U_BLOCKS, 256>>>(x);
    gemm_kernel<<<dim3(14, 8), 512, GEMM_SMEM>>>(w, y);
}

// round 10
// speedup vs baseline: 1.0172x; 1.0172x over previous
#include <cuda_runtime.h>
#include <cuda_bf16.h>

// y[i,a,b] = sum_{kj,kh,l} w[i,kj,kh,l] * U[a+kj-1, kh, b, l]   (zero pad on a+kj-1)
// U[ap,kh,b,l] = T(ap,kh,(b-1)%14, l+128) + T(ap,kh,b,l)
// T(ap,kh,b',c) = (0 <= b'+kh-1 < 14) ? x[c, ap, (b'+kh-2) mod 14] : 0

#define U_ELEMS (14 * 3 * 14 * 128)     // 75264
#define W_ELEMS (256 * 1152)            // 294912
#define U_BLOCKS 294                     // 294*256 == 75264
#define W_BLOCKS 1152                    // 1152*256 == 294912
#define GEMM_SMEM (16128 * 4)            // 64512 B: [9][14][128] floats (>= 57344 red)

__device__ float g_U[U_ELEMS];          // [ap][kh][b][l]
__device__ float g_Wt[W_ELEMS];         // packed: [k/4][i=256][4]  (i-coalesced)

// Fused prep: blocks [0,294) build U; blocks [294,1446) transpose/pack w.
__global__ void prep_kernel(const float* __restrict__ x, const float* __restrict__ w) {
    if (blockIdx.x < U_BLOCKS) {
        int e = blockIdx.x * 256 + threadIdx.x;      // < 75264
        int l  = e & 127;
        int b  = (e >> 7) % 14;
        int kh = (e / (128 * 14)) % 3;
        int ap = e / (128 * 14 * 3);

        float val = 0.0f;
        int t = b + kh - 1;
        if (t >= 0 && t < 14) {
            int wsrc = t - 1; if (wsrc < 0) wsrc += 14;
            val += x[l * 196 + ap * 14 + wsrc];
        }
        int bm = b - 1; if (bm < 0) bm += 14;
        int t1 = bm + kh - 1;
        if (t1 >= 0 && t1 < 14) {
            int wsrc = t1 - 1; if (wsrc < 0) wsrc += 14;
            val += x[(l + 128) * 196 + ap * 14 + wsrc];
        }
        g_U[e] = val;
    } else {
        int e = (blockIdx.x - U_BLOCKS) * 256 + threadIdx.x;  // < 294912, coalesced read
        int i = e / 1152;
        int k = e - i * 1152;
        g_Wt[(k >> 2) * 1024 + i * 4 + (k & 3)] = w[e];
    }
}

// Grid (a=14, i-tile=8), 1024 threads = 32 warps (8 per SMSP for latency hiding).
// lane = output channel (i0+lane); K split across 32 warps (36 k = 9 float4 each).
// w: coalesced LDG.128 from packed g_Wt. u: broadcast LDS.128 (1 crossbar cycle).
__global__ __launch_bounds__(1024, 1)
void gemm_kernel(float* __restrict__ y) {
    extern __shared__ float u_s[];       // [kq=9][b=14][l=128] = 16128 floats; reused as red

    const int a   = blockIdx.x;          // 0..13
    const int i0  = blockIdx.y * 32;
    const int tid = threadIdx.x;

    // ---- stage U rows ap = a-1 .. a+1 (zero outside [0,14)) ----
    float4* u4s = (float4*)u_s;
#pragma unroll
    for (int it = 0; it < 4; it++) {
        int idx = it * 1024 + tid;                   // < 4096; valid < 4032
        if (idx < 4032) {
            int kj  = idx / 1344;                    // 5376/4
            int rem = idx - kj * 1344;
            int ap  = a - 1 + kj;
            float4 v = make_float4(0.f, 0.f, 0.f, 0.f);
            if (ap >= 0 && ap < 14) v = ((const float4*)g_U)[ap * 1344 + rem];
            u4s[idx] = v;
        }
    }
    __syncthreads();

    const int warp = tid >> 5;           // 0..31
    const int lane = tid & 31;

    float acc[14];
#pragma unroll
    for (int b = 0; b < 14; b++) acc[b] = 0.f;

    // w: lane reads float4 {k..k+3} for row i0+lane; consecutive lanes contiguous.
    const float4* wp = ((const float4*)g_Wt) + (warp * 9) * 256 + i0 + lane;
    const float4* u4 = (const float4*)u_s;
    const int k0 = warp * 36;

#pragma unroll 3
    for (int t = 0; t < 9; t++) {
        float4 wv = wp[t * 256];                     // coalesced LDG.128 (4 lines/warp)
        int k  = k0 + t * 4;
        int ub = (k >> 7) * 448 + ((k & 127) >> 2);  // float4 idx into u_s, b=0
#pragma unroll
        for (int b = 0; b < 14; b++) {
            float4 uv = u4[ub + b * 32];             // warp-broadcast LDS (1 cyc)
            acc[b] = fmaf(wv.x, uv.x, acc[b]);
            acc[b] = fmaf(wv.y, uv.y, acc[b]);
            acc[b] = fmaf(wv.z, uv.z, acc[b]);
            acc[b] = fmaf(wv.w, uv.w, acc[b]);
        }
    }

    __syncthreads();                                 // u_s now reusable as red buffer
    float* red = u_s;                                // [warp=32][b=14][lane=32] = 14336 floats
#pragma unroll
    for (int b = 0; b < 14; b++) red[(warp * 14 + b) * 32 + lane] = acc[b];
    __syncthreads();

    if (tid < 14 * 32) {
        int b = tid >> 5;
        int i = tid & 31;
        float s = 0.f;
#pragma unroll
        for (int wq = 0; wq < 32; wq++) s += red[(wq * 14 + b) * 32 + i];
        y[(i0 + i) * 196 + a * 14 + b] = s;
    }
}

extern "C" void kernel_launch(void* const* d_in, const int* in_sizes, int n_in,
                              void* d_out, int out_size) {
    const float* x = (const float*)d_in[0];
    const float* w = (const float*)d_in[1];
    float* y = (float*)d_out;

    cudaFuncSetAttribute(gemm_kernel,
                         cudaFuncAttributeMaxDynamicSharedMemorySize, GEMM_SMEM);

    prep_kernel<<<U_BLOCKS + W_BLOCKS, 256>>>(x, w);
    gemm_kernel<<<dim3(14, 8), 1024, GEMM_SMEM>>>(y);
}

// round 11
// speedup vs baseline: 1.0194x; 1.0022x over previous
#include <cuda_runtime.h>
#include <cuda_bf16.h>

// y[i,a,b] = sum_{kj,kh,l} w[i,kj,kh,l] * U[a+kj-1, kh, b, l]   (zero pad on a+kj-1)
// U[ap,kh,b,l] = T(ap,kh,(b-1)%14, l+128) + T(ap,kh,b,l)
// T(ap,kh,b',c) = (0 <= b'+kh-1 < 14) ? x[c, ap, (b'+kh-2) mod 14] : 0

#define U_ELEMS (14 * 3 * 14 * 128)     // 75264
#define W_ELEMS (256 * 1152)            // 294912
#define U_BLOCKS 294                     // 294*256 == 75264
#define W_BLOCKS 1152                    // 1152*256 == 294912
#define GEMM_SMEM (16128 * 4)            // 64512 B: [b=14][k=1152] floats

__device__ float g_U[U_ELEMS];          // [ap][kh][b][l]
__device__ float g_Wt[W_ELEMS];         // packed: [k/4][i=256][4]  (i-coalesced)

// Fused prep: blocks [0,294) build U; blocks [294,1446) transpose/pack w.
__global__ void prep_kernel(const float* __restrict__ x, const float* __restrict__ w) {
    if (blockIdx.x < U_BLOCKS) {
        int e = blockIdx.x * 256 + threadIdx.x;      // < 75264
        int l  = e & 127;
        int b  = (e >> 7) % 14;
        int kh = (e / (128 * 14)) % 3;
        int ap = e / (128 * 14 * 3);

        float val = 0.0f;
        int t = b + kh - 1;
        if (t >= 0 && t < 14) {
            int wsrc = t - 1; if (wsrc < 0) wsrc += 14;
            val += x[l * 196 + ap * 14 + wsrc];
        }
        int bm = b - 1; if (bm < 0) bm += 14;
        int t1 = bm + kh - 1;
        if (t1 >= 0 && t1 < 14) {
            int wsrc = t1 - 1; if (wsrc < 0) wsrc += 14;
            val += x[(l + 128) * 196 + ap * 14 + wsrc];
        }
        g_U[e] = val;
    } else {
        int e = (blockIdx.x - U_BLOCKS) * 256 + threadIdx.x;  // < 294912, coalesced read
        int i = e / 1152;
        int k = e - i * 1152;
        g_Wt[(k >> 2) * 1024 + i * 4 + (k & 3)] = w[e];
    }
}

// Grid (a=14, i-tile=8), 512 threads = 16 warps. lane = channel i0+lane.
// K split over 16 warps (72 k = 18 float4 each). u_s[b][k-linear]: one broadcast
// LDS.128 (ulonglong2) = two ready f32x2 pairs; w ulonglong2 = matching pairs.
// 28 FFMA2 per iter replaces 56 FFMA — halves the per-SMSP issue budget.
__global__ __launch_bounds__(512, 1)
void gemm_kernel(float* __restrict__ y) {
    extern __shared__ float u_s[];       // [b=14][k=1152] = 16128 floats; reused as red

    const int a   = blockIdx.x;          // 0..13
    const int i0  = blockIdx.y * 32;
    const int tid = threadIdx.x;

    // ---- stage u_s[b][kj*384+kh*128+l] from g_U rows ap = a-1..a+1 ----
    float4* u4s = (float4*)u_s;
#pragma unroll
    for (int it = 0; it < 8; it++) {
        int idx = it * 512 + tid;                    // < 4096; valid < 4032
        if (idx < 4032) {
            int b  = idx / 288;                      // 1152/4
            int r  = idx - b * 288;
            int kj = r / 96;
            int r2 = r - kj * 96;                    // kh*32 + l4
            int ap = a - 1 + kj;
            float4 v = make_float4(0.f, 0.f, 0.f, 0.f);
            if (ap >= 0 && ap < 14)
                v = ((const float4*)g_U)[ap * 1344 + (r2 >> 5) * 448 + b * 32 + (r2 & 31)];
            u4s[b * 288 + r] = v;
        }
    }
    __syncthreads();

    const int warp = tid >> 5;           // 0..15
    const int lane = tid & 31;

    unsigned long long acc2[14];
#pragma unroll
    for (int b = 0; b < 14; b++) acc2[b] = 0ull;

    // w: lane reads {k..k+3} of row i0+lane as 2 f32x2 pairs; lanes contiguous.
    const ulonglong2* wp = ((const ulonglong2*)g_Wt) + (warp * 18) * 256 + i0 + lane;
    const ulonglong2* up = ((const ulonglong2*)u_s) + warp * 18;

#pragma unroll 3
    for (int t = 0; t < 18; t++) {
        ulonglong2 wv = wp[t * 256];                 // coalesced LDG.128
#pragma unroll
        for (int b = 0; b < 14; b++) {
            ulonglong2 uv = up[b * 288 + t];         // broadcast LDS.128 = 2 pairs
            asm("fma.rn.f32x2 %0, %1, %2, %0;" : "+l"(acc2[b]) : "l"(wv.x), "l"(uv.x));
            asm("fma.rn.f32x2 %0, %1, %2, %0;" : "+l"(acc2[b]) : "l"(wv.y), "l"(uv.y));
        }
    }

    __syncthreads();                                 // u_s now reusable as red buffer
    float* red = u_s;                                // [warp=16][b=14][lane=32] = 7168
#pragma unroll
    for (int b = 0; b < 14; b++) {
        float lo, hi;
        asm("mov.b64 {%0, %1}, %2;" : "=f"(lo), "=f"(hi) : "l"(acc2[b]));
        red[(warp * 14 + b) * 32 + lane] = lo + hi;
    }
    __syncthreads();

    if (tid < 14 * 32) {
        int b = tid >> 5;
        int i = tid & 31;
        float s = 0.f;
#pragma unroll
        for (int wq = 0; wq < 16; wq++) s += red[(wq * 14 + b) * 32 + i];
        y[(i0 + i) * 196 + a * 14 + b] = s;
    }
}

extern "C" void kernel_launch(void* const* d_in, const int* in_sizes, int n_in,
                              void* d_out, int out_size) {
    const float* x = (const float*)d_in[0];
    const float* w = (const float*)d_in[1];
    float* y = (float*)d_out;

    cudaFuncSetAttribute(gemm_kernel,
                         cudaFuncAttributeMaxDynamicSharedMemorySize, GEMM_SMEM);

    prep_kernel<<<U_BLOCKS + W_BLOCKS, 256>>>(x, w);
    gemm_kernel<<<dim3(14, 8), 512, GEMM_SMEM>>>(y);
}